// round 2
// baseline (speedup 1.0000x reference)
#include <cuda_runtime.h>
#include <cuda_bf16.h>

// RoPE: out[b,h,s,2i]   = cos(p_s * f_i) * x[...,2i]   - sin(p_s * f_i) * x[...,2i+1]
//       out[b,h,s,2i+1] = sin(p_s * f_i) * x[...,2i]   + cos(p_s * f_i) * x[...,2i+1]
// f_i = THETA^(-2i/d), d=128, THETA=10000.
//
// Strategy: precompute [seq, d/2] cos/sin table (2MB, L2-resident) with a tiny
// kernel, then a pure-streaming float4 kernel does the rotation (HBM-bound).

#define D_MODEL 128
#define D_HALF  64
#define D_VEC4  32           // D_MODEL / 4
#define MAX_SEQ 8192

// cos/sin table: laid out as float2 {cos, sin} per (s, i). Declared as float4
// so the main kernel can load two consecutive pairs with one LDG.128.
__device__ float4 g_tab4[MAX_SEQ * D_HALF / 2];

// ---------------------------------------------------------------------------
// Table builder. token_positions may be stored as int64 or int32 depending on
// how the harness serialized it; detect from the first 8 int32 words (an int64
// little-endian array of small positives has zeros at odd int32 indices).
// ---------------------------------------------------------------------------
__global__ void rope_build_table(const void* __restrict__ tok_pos, int seq) {
    int idx = blockIdx.x * blockDim.x + threadIdx.x;
    if (idx >= seq * D_HALF) return;
    int s = idx / D_HALF;
    int i = idx - s * D_HALF;

    const int* v32 = (const int*)tok_pos;
    bool is64;
    if (seq >= 8) {
        // int64 small-value arrays: odd int32 words are all zero.
        // int32 arange: v32[1] == 1 != 0.
        is64 = (v32[1] == 0 && v32[3] == 0 && v32[5] == 0 && v32[7] == 0);
    } else {
        is64 = false;
    }

    long long p;
    if (is64) p = ((const long long*)tok_pos)[s];
    else      p = (long long)v32[s];

    // inv_freq = 10000^(-2i/d) = exp2(-(2i/d) * log2(10000))
    const float LOG2_THETA = 13.287712379549449f; // log2(10000)
    float e   = (float)(2 * i) * (1.0f / (float)D_MODEL);
    float inv = exp2f(-e * LOG2_THETA);
    float ang = (float)p * inv;

    float sn, cs;
    sincosf(ang, &sn, &cs);   // accurate (non-intrinsic) path

    ((float2*)g_tab4)[(size_t)s * D_HALF + i] = make_float2(cs, sn);
}

// ---------------------------------------------------------------------------
// Main streaming kernel: one thread = one float4 of x (2 rotation pairs).
// Layout of x is [B, H, S, D] with D=128 contiguous, so within a row of 32
// float4s the table row is shared; table reads are L2/L1 hot.
// ---------------------------------------------------------------------------
__global__ void __launch_bounds__(256)
rope_apply(const float4* __restrict__ x, float4* __restrict__ out,
           int seq, long long n4) {
    long long idx = (long long)blockIdx.x * blockDim.x + threadIdx.x;
    if (idx >= n4) return;

    int d4 = (int)(idx & (D_VEC4 - 1));            // which float4 within the head dim
    int s  = (int)((idx >> 5) % (long long)seq);   // sequence index (D_VEC4 = 32 = 1<<5)

    float4 v = x[idx];
    // (cos0, sin0, cos1, sin1) for pairs 2*d4 and 2*d4+1
    float4 t = g_tab4[(size_t)s * D_VEC4 + d4];

    float4 o;
    o.x = fmaf(t.x, v.x, -t.y * v.y);   // cos0*e0 - sin0*o0
    o.y = fmaf(t.y, v.x,  t.x * v.y);   // sin0*e0 + cos0*o0
    o.z = fmaf(t.z, v.z, -t.w * v.w);
    o.w = fmaf(t.w, v.z,  t.x == t.x ? t.z * v.w : 0.f); // (keep simple: cos1*o1)
    o.w = fmaf(t.w, v.z,  t.z * v.w);

    out[idx] = o;
}

// ---------------------------------------------------------------------------
extern "C" void kernel_launch(void* const* d_in, const int* in_sizes, int n_in,
                              void* d_out, int out_size) {
    const float* x = (const float*)d_in[0];
    const void*  tp = d_in[1];

    long long n_elem = (long long)in_sizes[0];
    int seq = in_sizes[1];
    if (seq > MAX_SEQ) seq = MAX_SEQ;

    long long n4 = n_elem / 4;

    // 1) Build cos/sin table (tiny).
    {
        int total = seq * D_HALF;
        int threads = 256;
        int blocks = (total + threads - 1) / threads;
        rope_build_table<<<blocks, threads>>>(tp, seq);
    }

    // 2) Streaming rotation.
    {
        int threads = 256;
        long long blocks = (n4 + threads - 1) / threads;
        rope_apply<<<(unsigned int)blocks, threads>>>(
            (const float4*)x, (float4*)d_out, seq, n4);
    }
}

// round 5
// speedup vs baseline: 1.0636x; 1.0636x over previous
#include <cuda_runtime.h>
#include <cuda_bf16.h>

// RoPE: out[...,2i]   = cos(p*f_i)*x[...,2i] - sin(p*f_i)*x[...,2i+1]
//       out[...,2i+1] = sin(p*f_i)*x[...,2i] + cos(p*f_i)*x[...,2i+1]
// f_i = THETA^(-2i/d), d=128, THETA=10000.
//
// Two kernels: tiny sincos table build ([seq, d/2], 2MB, L2-resident), then a
// pure-streaming rotation kernel (HBM-bound). R3: 4 float4s per thread
// (front-batched loads for MLP), 32-bit indexing, streaming cache hints.

#define D_MODEL 128
#define D_HALF  64
#define D_VEC4  32           // D_MODEL / 4
#define MAX_SEQ 8192

// {cos,sin} pairs; float4 = two consecutive pairs -> one LDG.128 in main loop.
__device__ float4 g_tab4[MAX_SEQ * D_HALF / 2];

// ---------------------------------------------------------------------------
// Table builder. token_positions may be int64 or int32; detect from the first
// 8 int32 words (little-endian int64 small positives have zero odd words).
// ---------------------------------------------------------------------------
__global__ void rope_build_table(const void* __restrict__ tok_pos, int seq) {
    int idx = blockIdx.x * blockDim.x + threadIdx.x;
    if (idx >= seq * D_HALF) return;
    int s = idx >> 6;          // / D_HALF
    int i = idx & (D_HALF - 1);

    const int* v32 = (const int*)tok_pos;
    bool is64 = false;
    if (seq >= 8)
        is64 = (v32[1] == 0 && v32[3] == 0 && v32[5] == 0 && v32[7] == 0);

    long long p = is64 ? ((const long long*)tok_pos)[s] : (long long)v32[s];

    const float LOG2_THETA = 13.287712379549449f; // log2(10000)
    float e   = (float)(2 * i) * (1.0f / (float)D_MODEL);
    float inv = exp2f(-e * LOG2_THETA);
    float ang = (float)p * inv;

    float sn, cs;
    sincosf(ang, &sn, &cs);   // accurate path

    ((float2*)g_tab4)[(size_t)s * D_HALF + i] = make_float2(cs, sn);
}

// ---------------------------------------------------------------------------
// Main streaming kernel: thread handles 4 float4s at stride q = n4/4.
// All four streams are warp-coalesced. 32-bit indices throughout.
// smask = seq-1 if seq is a power of two, else 0 (use %).
// ---------------------------------------------------------------------------
__device__ __forceinline__ float4 rope_rot(float4 v, float4 t) {
    float4 o;
    o.x = fmaf(t.x, v.x, -t.y * v.y);
    o.y = fmaf(t.y, v.x,  t.x * v.y);
    o.z = fmaf(t.z, v.z, -t.w * v.w);
    o.w = fmaf(t.w, v.z,  t.z * v.w);
    return o;
}

__global__ void __launch_bounds__(256)
rope_apply4(const float4* __restrict__ x, float4* __restrict__ out,
            unsigned int seq, unsigned int smask, unsigned int q) {
    unsigned int i = blockIdx.x * blockDim.x + threadIdx.x;
    if (i >= q) return;

    unsigned int i0 = i, i1 = i + q, i2 = i + 2u * q, i3 = i + 3u * q;

    // Front-batched streaming loads (evict-first: data never reused).
    float4 v0 = __ldcs(x + i0);
    float4 v1 = __ldcs(x + i1);
    float4 v2 = __ldcs(x + i2);
    float4 v3 = __ldcs(x + i3);

    unsigned int r0 = i0 >> 5, r1 = i1 >> 5, r2 = i2 >> 5, r3 = i3 >> 5;
    unsigned int s0, s1, s2, s3;
    if (smask) { s0 = r0 & smask; s1 = r1 & smask; s2 = r2 & smask; s3 = r3 & smask; }
    else       { s0 = r0 % seq;   s1 = r1 % seq;   s2 = r2 % seq;   s3 = r3 % seq;   }

    float4 t0 = g_tab4[s0 * D_VEC4 + (i0 & (D_VEC4 - 1))];
    float4 t1 = g_tab4[s1 * D_VEC4 + (i1 & (D_VEC4 - 1))];
    float4 t2 = g_tab4[s2 * D_VEC4 + (i2 & (D_VEC4 - 1))];
    float4 t3 = g_tab4[s3 * D_VEC4 + (i3 & (D_VEC4 - 1))];

    __stcs(out + i0, rope_rot(v0, t0));
    __stcs(out + i1, rope_rot(v1, t1));
    __stcs(out + i2, rope_rot(v2, t2));
    __stcs(out + i3, rope_rot(v3, t3));
}

// Fallback for n4 not divisible by 4 (not expected for this shape).
__global__ void __launch_bounds__(256)
rope_apply1(const float4* __restrict__ x, float4* __restrict__ out,
            unsigned int seq, unsigned int smask,
            unsigned int start, unsigned int n4) {
    unsigned int i = start + blockIdx.x * blockDim.x + threadIdx.x;
    if (i >= n4) return;
    unsigned int r = i >> 5;
    unsigned int s = smask ? (r & smask) : (r % seq);
    float4 v = __ldcs(x + i);
    float4 t = g_tab4[s * D_VEC4 + (i & (D_VEC4 - 1))];
    __stcs(out + i, rope_rot(v, t));
}

// ---------------------------------------------------------------------------
extern "C" void kernel_launch(void* const* d_in, const int* in_sizes, int n_in,
                              void* d_out, int out_size) {
    const float* x  = (const float*)d_in[0];
    const void*  tp = d_in[1];

    unsigned int n_elem = (unsigned int)in_sizes[0];
    unsigned int seq = (unsigned int)in_sizes[1];
    if (seq > MAX_SEQ) seq = MAX_SEQ;
    unsigned int smask = ((seq & (seq - 1)) == 0) ? (seq - 1) : 0u;

    unsigned int n4 = n_elem / 4;
    unsigned int q  = n4 / 4;          // elements (float4s) per stream

    // 1) cos/sin table
    {
        int total = (int)(seq * D_HALF);
        int threads = 256;
        int blocks = (total + threads - 1) / threads;
        rope_build_table<<<blocks, threads>>>(tp, (int)seq);
    }

    // 2) streaming rotation, 4 float4s/thread
    if (q) {
        int threads = 256;
        unsigned int blocks = (q + threads - 1) / threads;
        rope_apply4<<<blocks, threads>>>((const float4*)x, (float4*)d_out,
                                         seq, smask, q);
    }
    // tail (n4 % 4 leftovers)
    unsigned int done = q * 4u;
    if (done < n4) {
        unsigned int rem = n4 - done;
        int threads = 256;
        unsigned int blocks = (rem + threads - 1) / threads;
        rope_apply1<<<blocks, threads>>>((const float4*)x, (float4*)d_out,
                                         seq, smask, done, n4);
    }
}